// round 2
// baseline (speedup 1.0000x reference)
#include <cuda_runtime.h>
#include <math_constants.h>

#define N_OSC   60
#define BDIM    128
#define TI      10          // i-tile size (accumulator block)
#define NTILES  (N_OSC/TI)  // 6
#define STEPS   10

// shared layout (floats): Keff[3600] | S[128*60] | C[128*60] | Th[60*128] | Om[64]
#define SMEM_FLOATS (3600 + BDIM*60 + BDIM*60 + 60*BDIM + 64)
#define SMEM_BYTES  (SMEM_FLOATS * 4)

__global__ __launch_bounds__(BDIM, 2)
void kuramoto_kernel(const float* __restrict__ theta,
                     const float* __restrict__ K,
                     const float* __restrict__ omega,
                     const float* __restrict__ p_Kg,
                     const float* __restrict__ p_cm,
                     const float* __restrict__ p_gate,
                     const float* __restrict__ p_csf,
                     const float* __restrict__ p_ds,
                     const float* __restrict__ p_rt,
                     float* __restrict__ out,
                     int B)
{
    extern __shared__ float smem[];
    float* sK  = smem;                       // K_eff = K * coupling_mod  (ref-exact)
    float* sS  = sK  + 3600;                 // [tid][60] per-thread sin snapshot
    float* sC  = sS  + BDIM * 60;
    float* sTh = sC  + BDIM * 60;            // [j][tid] stride BDIM
    float* sOm = sTh + 60 * BDIM;            // raw omega

    const int tid = threadIdx.x;
    const int b   = blockIdx.x * BDIM + tid;

    // ---- scalar factors, emulating the reference's fp32 op order exactly ----
    // critical_factor = 1/(1 + csf*rt); eff_dt = 0.1*cf
    const float cf     = __fdiv_rn(1.0f, __fadd_rn(1.0f, __fmul_rn(p_csf[0], p_rt[0])));
    const float eff_dt = __fmul_rn(0.1f, cf);
    // boost = 1 + gate*ds; scale = Kg*boost/n
    const float boost  = __fadd_rn(1.0f, __fmul_rn(p_gate[0], p_ds[0]));
    const float scale  = __fdiv_rn(__fmul_rn(p_Kg[0], boost), (float)N_OSC);

    // K_eff = K * coupling_mod, elementwise — bitwise identical to reference
    {
        const float cm = p_cm[0];
        for (int idx = tid; idx < 3600; idx += BDIM) sK[idx] = __fmul_rn(K[idx], cm);
    }
    if (tid < N_OSC) sOm[tid] = omega[tid];

    // Load this thread's batch row of theta (coalesced-per-thread float4).
    const float4* th4 = (const float4*)(theta + (size_t)b * N_OSC);
    #pragma unroll
    for (int j4 = 0; j4 < 15; ++j4) {
        float4 v = th4[j4];
        sTh[(j4*4 + 0)*BDIM + tid] = v.x;
        sTh[(j4*4 + 1)*BDIM + tid] = v.y;
        sTh[(j4*4 + 2)*BDIM + tid] = v.z;
        sTh[(j4*4 + 3)*BDIM + tid] = v.w;
    }
    __syncthreads();   // only sync needed: K/Om cooperative load

    for (int step = 0; step < STEPS; ++step) {
        // ---- snapshot sin/cos of current theta (fast path; feeds coupling only) ----
        #pragma unroll
        for (int j4 = 0; j4 < 15; ++j4) {
            float4 sv, cv;
            __sincosf(sTh[(j4*4 + 0)*BDIM + tid], &sv.x, &cv.x);
            __sincosf(sTh[(j4*4 + 1)*BDIM + tid], &sv.y, &cv.y);
            __sincosf(sTh[(j4*4 + 2)*BDIM + tid], &sv.z, &cv.z);
            __sincosf(sTh[(j4*4 + 3)*BDIM + tid], &sv.w, &cv.w);
            *(float4*)&sS[tid*60 + j4*4] = sv;
            *(float4*)&sC[tid*60 + j4*4] = cv;
        }
        // no sync: each thread reads only its own rows; K is read-only

        // ---- matvec (Keff @ s, Keff @ c) in i-tiles, then ref-exact update ----
        for (int it = 0; it < NTILES; ++it) {
            const int i0 = it * TI;
            float accS[TI], accC[TI];
            #pragma unroll
            for (int u = 0; u < TI; ++u) { accS[u] = 0.f; accC[u] = 0.f; }

            for (int j4 = 0; j4 < 15; ++j4) {
                float4 s4 = *(const float4*)&sS[tid*60 + j4*4];
                float4 c4 = *(const float4*)&sC[tid*60 + j4*4];
                #pragma unroll
                for (int u = 0; u < TI; ++u) {
                    float4 k4 = *(const float4*)&sK[(i0 + u)*60 + j4*4]; // warp-broadcast
                    accS[u] = fmaf(k4.x, s4.x, fmaf(k4.y, s4.y,
                              fmaf(k4.z, s4.z, fmaf(k4.w, s4.w, accS[u]))));
                    accC[u] = fmaf(k4.x, c4.x, fmaf(k4.y, c4.y,
                              fmaf(k4.z, c4.z, fmaf(k4.w, c4.w, accC[u]))));
                }
            }

            #pragma unroll
            for (int u = 0; u < TI; ++u) {
                const int i = i0 + u;
                const float si = sS[tid*60 + i];
                const float ci = sC[tid*60 + i];
                // coupling_i = cos(th_i)*sum(Keff*sin) - sin(th_i)*sum(Keff*cos)
                const float coupling = __fadd_rn(__fmul_rn(ci, accS[u]),
                                                 -__fmul_rn(si, accC[u]));
                // reference op order: t = th + eff_dt*(omega + scale*coupling)
                const float tmp = __fadd_rn(sOm[i], __fmul_rn(scale, coupling));
                const float t   = __fadd_rn(sTh[i*BDIM + tid], __fmul_rn(eff_dt, tmp));
                // reference wrap: atan2(sin t, cos t) — precise libdevice fns
                const float sw = sinf(t);
                const float cw = cosf(t);
                sTh[i*BDIM + tid] = atan2f(sw, cw);
            }
        }
    }

    // ---- output: theta [b*60 + j], then coherence at [B*60 + b] ----
    float ssum = 0.f, csum = 0.f;
    float4* o4 = (float4*)(out + (size_t)b * N_OSC);
    #pragma unroll
    for (int j4 = 0; j4 < 15; ++j4) {
        float4 v;
        v.x = sTh[(j4*4 + 0)*BDIM + tid];
        v.y = sTh[(j4*4 + 1)*BDIM + tid];
        v.z = sTh[(j4*4 + 2)*BDIM + tid];
        v.w = sTh[(j4*4 + 3)*BDIM + tid];
        o4[j4] = v;
        ssum += sinf(v.x); csum += cosf(v.x);
        ssum += sinf(v.y); csum += cosf(v.y);
        ssum += sinf(v.z); csum += cosf(v.z);
        ssum += sinf(v.w); csum += cosf(v.w);
    }
    ssum = __fmul_rn(ssum, 1.0f / (float)N_OSC);
    csum = __fmul_rn(csum, 1.0f / (float)N_OSC);
    out[(size_t)B * N_OSC + b] = sqrtf(__fadd_rn(__fmul_rn(csum, csum),
                                                 __fmul_rn(ssum, ssum)));
}

extern "C" void kernel_launch(void* const* d_in, const int* in_sizes, int n_in,
                              void* d_out, int out_size)
{
    const float* theta = (const float*)d_in[0];
    const float* K     = (const float*)d_in[1];
    const float* omega = (const float*)d_in[2];
    const float* p_Kg   = (const float*)d_in[3];
    const float* p_cm   = (const float*)d_in[4];
    const float* p_gate = (const float*)d_in[5];
    const float* p_csf  = (const float*)d_in[6];
    const float* p_ds   = (const float*)d_in[7];
    const float* p_rt   = (const float*)d_in[8];
    float* out = (float*)d_out;

    const int B = in_sizes[0] / N_OSC;
    const int grid = B / BDIM;

    cudaFuncSetAttribute(kuramoto_kernel,
                         cudaFuncAttributeMaxDynamicSharedMemorySize, SMEM_BYTES);

    kuramoto_kernel<<<grid, BDIM, SMEM_BYTES>>>(
        theta, K, omega, p_Kg, p_cm, p_gate, p_csf, p_ds, p_rt, out, B);
}